// round 16
// baseline (speedup 1.0000x reference)
#include <cuda_runtime.h>
#include <cstdint>

// ---------------- problem constants ----------------
#define CIN   128
#define COUT  256
#define DTOT  1152
#define RCH   18
#define NCTA  296
#define NTILES 8192          // 1024 pixel groups x 8 channel groups (16x32 tiles)
#define NT_T  5632           // tensor-first pool (~69%)
#define NT_D  (NTILES - NT_T)

#define PADROW 36
#define PADIMG (34 * PADROW)

// ---------------- device scratch ----------------
__device__ unsigned g_mm[2] = {0u, 0u};
__device__ unsigned g_tkT, g_tkD;
__device__ __align__(16) signed char g_wq[RCH * 256 * 64];       // [r][m][64] permuted words
__device__ __align__(16) signed char g_xq[(size_t)RCH * 3 * 4 * 16384 * 16]; // [r][pl][seg][pix][16]
__device__ __align__(16) float g_xpad[16 * 128 * PADIMG];
__device__ int   g_ctab[DTOT];

// ---------------- helpers ----------------
__device__ __forceinline__ unsigned encf(float f) {
    int b = __float_as_int(f);
    return (b < 0) ? ~(unsigned)b : ((unsigned)b | 0x80000000u);
}
__device__ __forceinline__ float decf(unsigned u) {
    int b = (u & 0x80000000u) ? (int)(u & 0x7fffffffu) : ~(int)u;
    return __int_as_float(b);
}
__device__ __forceinline__ void imma(int* d, const unsigned* a,
                                     unsigned b0, unsigned b1) {
    asm volatile(
        "mma.sync.aligned.m16n8k32.row.col.s32.s8.s8.s32 "
        "{%0,%1,%2,%3}, {%4,%5,%6,%7}, {%8,%9}, {%0,%1,%2,%3};"
        : "+r"(d[0]), "+r"(d[1]), "+r"(d[2]), "+r"(d[3])
        : "r"(a[0]), "r"(a[1]), "r"(a[2]), "r"(a[3]),
          "r"(b0), "r"(b1));
}
__device__ __forceinline__ unsigned prmt(unsigned a, unsigned b, unsigned c) {
    unsigned r;
    asm("prmt.b32 %0, %1, %2, %3;" : "=r"(r) : "r"(a), "r"(b), "r"(c));
    return r;
}
__device__ __forceinline__ unsigned pack_b0(int v0, int v1, int v2, int v3) {
    return prmt(prmt((unsigned)v0, (unsigned)v1, 0x0040),
                prmt((unsigned)v2, (unsigned)v3, 0x0040), 0x5410);
}
__device__ __forceinline__ unsigned getc(uint4 v, int i) {
    switch (i & 3) {
        case 0: return v.x;
        case 1: return v.y;
        case 2: return v.z;
        default: return v.w;
    }
}

// ---------------- pre-kernels ----------------
__global__ void k_minmax(const float* __restrict__ w, int n) {
    unsigned mx = 0u, mn = 0u;
    for (int i = blockIdx.x * blockDim.x + threadIdx.x; i < n;
         i += gridDim.x * blockDim.x) {
        float f = w[i];
        unsigned e0 = encf(f), e1 = encf(-f);
        mx = mx > e0 ? mx : e0;
        mn = mn > e1 ? mn : e1;
    }
    #pragma unroll
    for (int o = 16; o; o >>= 1) {
        unsigned a = __shfl_xor_sync(0xffffffffu, mx, o);
        unsigned b = __shfl_xor_sync(0xffffffffu, mn, o);
        mx = mx > a ? mx : a;
        mn = mn > b ? mn : b;
    }
    if ((threadIdx.x & 31) == 0) {
        atomicMax(&g_mm[0], mx);
        atomicMax(&g_mm[1], mn);
    }
}

// quantize to s8, layout [r][m][64] with word permutation p = 4*(W&3)+(W>>2)
__global__ void k_quant(const float* __restrict__ w) {
    int idx = blockIdx.x * blockDim.x + threadIdx.x;
    if (idx >= COUT * DTOT) return;
    float mx = decf(g_mm[0]);
    float mn = -decf(g_mm[1]);
    float scale = 15.0f / (mx - mn + 1e-9f);
    int m = idx / DTOT;
    int d = idx - m * DTOT;
    float q = fminf(fmaxf(rintf(w[idx] * scale), -7.0f), 7.0f);
    int r = d >> 6, kk = d & 63;
    int W = kk >> 2;
    int p = 4 * (W & 3) + (W >> 2);
    g_wq[r * 16384 + m * 64 + p * 4 + (kk & 3)] = (signed char)(int)q;
}

__global__ void k_pad(const float* __restrict__ inp) {
    int idx = blockIdx.x * blockDim.x + threadIdx.x;
    if (idx == 0) { g_tkT = 0u; g_tkD = 0u; }
    if (idx < DTOT) {
        int c = idx / 9, e = idx - 9 * c;
        int dy = e / 3, dx = e - 3 * dy;
        g_ctab[idx] = c * PADIMG + dy * PADROW + dx;
    }
    const int N4 = 16 * 128 * (PADIMG / 4);
    if (idx >= N4) return;
    int bc  = idx / (PADIMG / 4);
    int rem = idx - bc * (PADIMG / 4);
    int yy  = rem / (PADROW / 4);
    int c4  = rem - yy * (PADROW / 4);
    const float* src = inp + bc * 1024 + (yy - 1) * 32;
    float4 v;
    #pragma unroll
    for (int j = 0; j < 4; j++) {
        int x = c4 * 4 + j;
        float f = 0.0f;
        if ((unsigned)(yy - 1) < 32u && (unsigned)(x - 1) < 32u)
            f = src[x - 1];
        ((float*)&v)[j] = f;
    }
    *(float4*)&g_xpad[(size_t)bc * PADIMG + yy * PADROW + c4 * 4] = v;
}

__global__ __launch_bounds__(256)
void k_im2col() {
    __shared__ int s_ct[64];
    const int bid = blockIdx.x;
    const int r   = bid >> 6;
    const int pix = ((bid & 63) << 8) + threadIdx.x;
    const int b   = pix >> 10;
    const int p10 = pix & 1023;
    const int py  = p10 >> 5;
    const int px  = p10 & 31;
    const float* __restrict__ xb =
        g_xpad + (size_t)b * (128 * PADIMG) + py * PADROW + px;

    if (threadIdx.x < 64) s_ct[threadIdx.x] = g_ctab[r * 64 + threadIdx.x];
    __syncthreads();

    #pragma unroll
    for (int seg = 0; seg < 4; seg++) {
        unsigned lo4[4], md4[4], hi4[4];
        #pragma unroll
        for (int w = 0; w < 4; w++) {
            int vi[4];
            #pragma unroll
            for (int e = 0; e < 4; e++) {
                float v = xb[s_ct[seg * 16 + w * 4 + e]];
                vi[e] = __float2int_rn(v * 524288.0f);
            }
            int t0 = (vi[0] + 128) >> 8, t1 = (vi[1] + 128) >> 8;
            int t2 = (vi[2] + 128) >> 8, t3 = (vi[3] + 128) >> 8;
            int u0 = (t0 + 128) >> 8, u1 = (t1 + 128) >> 8;
            int u2 = (t2 + 128) >> 8, u3 = (t3 + 128) >> 8;
            lo4[w] = pack_b0(vi[0], vi[1], vi[2], vi[3]);
            md4[w] = pack_b0(t0, t1, t2, t3);
            hi4[w] = pack_b0(u0, u1, u2, u3);
        }
        size_t base = ((((size_t)r * 3 + 0) * 4 + seg) * 16384 + pix) * 16;
        *(uint4*)&g_xq[base] = make_uint4(hi4[0], hi4[1], hi4[2], hi4[3]);
        base = ((((size_t)r * 3 + 1) * 4 + seg) * 16384 + pix) * 16;
        *(uint4*)&g_xq[base] = make_uint4(md4[0], md4[1], md4[2], md4[3]);
        base = ((((size_t)r * 3 + 2) * 4 + seg) * 16384 + pix) * 16;
        *(uint4*)&g_xq[base] = make_uint4(lo4[0], lo4[1], lo4[2], lo4[3]);
    }
}

// ---------------- tensor-path tile: 16 pix x 32 ch ----------------
__device__ __noinline__ void tensor_tile(int tile, int lane,
                                         float* __restrict__ out) {
    const signed char* __restrict__ xq = g_xq;
    const signed char* __restrict__ wq = g_wq;
    const unsigned laneq = (unsigned)(lane >> 2);
    const unsigned lane4 = (unsigned)(lane & 3) * 4u;

    const int gp0 = (tile >> 3) * 16;
    const int ch0 = (tile & 7) * 32;

    unsigned pixoff[2];
    #pragma unroll
    for (int qh = 0; qh < 2; qh++)
        pixoff[qh] = (unsigned)(gp0 + (int)laneq + qh * 8) * 16u + lane4;

    unsigned cnt[4];
    #pragma unroll
    for (int i = 0; i < 4; i++) cnt[i] = 0u;

    #pragma unroll 1
    for (int r = 0; r < RCH; r++) {
        // A fragments: 16 LDG.32
        unsigned af[2][2][4];
        #pragma unroll
        for (int pl = 0; pl < 2; pl++) {
            const unsigned pbase = (unsigned)(r * 3 + pl) << 20;
            #pragma unroll
            for (int ks = 0; ks < 2; ks++)
                #pragma unroll
                for (int q = 0; q < 4; q++) {
                    const unsigned seg = (unsigned)(ks * 2 + (q >> 1));
                    af[pl][ks][q] = *(const unsigned*)
                        (xq + pbase + (seg << 18) + pixoff[q & 1]);
                }
        }
        // B fragments: 4 LDG.128 (permuted rows; comp j = word 4j + (lane&3))
        uint4 bv[4];
        #pragma unroll
        for (int ntl = 0; ntl < 4; ntl++) {
            const unsigned n = (unsigned)(ch0 + ntl * 8) + laneq;
            bv[ntl] = *(const uint4*)
                (wq + (unsigned)r * 16384u + n * 64u + lane4 * 4u);
        }

        #pragma unroll
        for (int ntl = 0; ntl < 4; ntl++) {
            int acc[4] = {0, 0, 0, 0};
            #pragma unroll
            for (int pl = 0; pl < 2; pl++) {
                if (pl) { acc[0] <<= 8; acc[1] <<= 8; acc[2] <<= 8; acc[3] <<= 8; }
                imma(acc, af[pl][0], bv[ntl].x, bv[ntl].y);   // ks=0: segs 0,1
                imma(acc, af[pl][1], bv[ntl].z, bv[ntl].w);   // ks=1: segs 2,3
            }

            unsigned inc = 0, cm = 0;
            #pragma unroll
            for (int q = 0; q < 4; q++) {
                int v = acc[q];
                inc |= ((unsigned)(~v) >> 31) << (8 * q);
                if ((unsigned)(v + 224) <= 448u) cm |= 1u << q;
            }
            cnt[ntl] += inc;

            while (cm) {
                const int q = __ffs(cm) - 1;
                cm &= cm - 1;
                const int row = gp0 + (int)laneq + ((q & 2) ? 8 : 0);
                const int col = ch0 + ntl * 8 + 2 * (lane & 3) + (q & 1);
                uint4 wr[4];
                #pragma unroll
                for (int e = 0; e < 4; e++)
                    wr[e] = *(const uint4*)
                        (wq + (unsigned)r * 16384u + (unsigned)col * 64u + e * 16u);
                int slo = 0;
                #pragma unroll
                for (int kk = 0; kk < 4; kk++) {    // A seg kk words 4kk..4kk+3
                    uint4 xl = *(const uint4*)
                        (xq + ((unsigned)(r * 3 + 2) << 20)
                            + ((unsigned)kk << 18) + (unsigned)row * 16u);
                    slo = __dp4a((int)xl.x, (int)getc(wr[0], kk), slo);
                    slo = __dp4a((int)xl.y, (int)getc(wr[1], kk), slo);
                    slo = __dp4a((int)xl.z, (int)getc(wr[2], kk), slo);
                    slo = __dp4a((int)xl.w, (int)getc(wr[3], kk), slo);
                }
                const int S = (acc[q] << 8) + slo;
                const unsigned ob = (unsigned)(~acc[q]) >> 31;
                const unsigned nb = (unsigned)(~S) >> 31;
                cnt[ntl] += (nb - ob) << (8 * q);
            }
        }
    }

    const int b   = gp0 >> 10;
    const int p10 = gp0 & 1023;
    float* __restrict__ ob = out + (size_t)b * (COUT * 1024) + p10;
    #pragma unroll
    for (int g = 0; g < 4; g++) {
        const int chb = ch0 + g * 8 + 2 * (lane & 3);
        #pragma unroll
        for (int q = 0; q < 4; q++) {
            const int cc = chb + (q & 1);
            const int pp = (lane >> 2) + ((q & 2) ? 8 : 0);
            ob[(size_t)cc * 1024 + pp] = (float)((cnt[g] >> (8 * q)) & 255u);
        }
    }
}

// ---------------- dp4a-path tile: 16 pix x 32 ch (1 ch per lane) ----------------
__device__ __noinline__ void dp4a_tile(int tile, int lane, uint4* As,
                                       float* __restrict__ out) {
    const signed char* __restrict__ xq = g_xq;
    const signed char* __restrict__ wq = g_wq;

    const int gp0 = (tile >> 3) * 16;
    const int ch0 = (tile & 7) * 32;
    const int c0  = ch0 + lane;

    unsigned cnt[4];
    #pragma unroll
    for (int i = 0; i < 4; i++) cnt[i] = 0u;

    #pragma unroll 1
    for (int r = 0; r < RCH; r++) {
        __syncwarp();
        // stage A slab (3 planes x 16 pix x 64B = 192 uint4)
        #pragma unroll
        for (int i = 0; i < 6; i++) {
            const int u   = lane + 32 * i;
            const int pl  = u >> 6;
            const int rem = u & 63;
            const int seg = rem >> 4;
            const int p   = rem & 15;
            uint4 v = *(const uint4*)
                (xq + ((unsigned)(r * 3 + pl) << 20) + ((unsigned)seg << 18)
                    + (unsigned)(gp0 + p) * 16u);
            As[(pl * 16 + p) * 4 + seg] = v;
        }
        // W: permuted row for this lane's channel, 4 LDG.128
        uint4 w[4];
        #pragma unroll
        for (int e = 0; e < 4; e++)
            w[e] = *(const uint4*)
                (wq + (unsigned)r * 16384u + (unsigned)c0 * 64u + e * 16u);
        __syncwarp();

        #pragma unroll
        for (int p = 0; p < 16; p++) {
            const uint4* ah = &As[(0 * 16 + p) * 4];
            const uint4* am = &As[(1 * 16 + p) * 4];
            int sh = 0, sm = 0;
            #pragma unroll
            for (int i = 0; i < 4; i++) {           // A seg i = words 4i..4i+3
                uint4 a = ah[i];
                sh = __dp4a((int)a.x, (int)getc(w[0], i), sh);
                sh = __dp4a((int)a.y, (int)getc(w[1], i), sh);
                sh = __dp4a((int)a.z, (int)getc(w[2], i), sh);
                sh = __dp4a((int)a.w, (int)getc(w[3], i), sh);
                uint4 m = am[i];
                sm = __dp4a((int)m.x, (int)getc(w[0], i), sm);
                sm = __dp4a((int)m.y, (int)getc(w[1], i), sm);
                sm = __dp4a((int)m.z, (int)getc(w[2], i), sm);
                sm = __dp4a((int)m.w, (int)getc(w[3], i), sm);
            }
            int s = (sh << 8) + sm;
            if ((unsigned)(s + 224) <= 448u) {
                const uint4* al = &As[(2 * 16 + p) * 4];
                int slo = 0;
                #pragma unroll
                for (int i = 0; i < 4; i++) {
                    uint4 a = al[i];
                    slo = __dp4a((int)a.x, (int)getc(w[0], i), slo);
                    slo = __dp4a((int)a.y, (int)getc(w[1], i), slo);
                    slo = __dp4a((int)a.z, (int)getc(w[2], i), slo);
                    slo = __dp4a((int)a.w, (int)getc(w[3], i), slo);
                }
                s = (s << 8) + slo;
            }
            cnt[p >> 2] += (((unsigned)(~s)) >> 31) << (8 * (p & 3));
        }
    }

    // store: 1 channel x 16 contiguous pixels (4 x STG.128)
    const int b   = gp0 >> 10;
    const int p10 = gp0 & 1023;
    float* __restrict__ o = out + (size_t)b * (COUT * 1024)
                          + (size_t)c0 * 1024 + p10;
    #pragma unroll
    for (int g = 0; g < 4; g++) {
        unsigned v = cnt[g];
        float4 f;
        f.x = (float)( v        & 255u);
        f.y = (float)((v >>  8) & 255u);
        f.z = (float)((v >> 16) & 255u);
        f.w = (float)((v >> 24) & 255u);
        *(float4*)&o[g * 4] = f;
    }
}

// ---------------- main kernel: dual-pipe (IMMA + dp4a) ----------------
__global__ __launch_bounds__(256, 2)
void k_onn_main(float* __restrict__ out) {
    __shared__ __align__(16) uint4 s_a[4][192];

    const int tid  = threadIdx.x;
    const int lane = tid & 31;
    const int wid  = tid >> 5;

    if (wid < 4) {
        for (;;) {
            int t;
            if (lane == 0) t = (int)atomicAdd(&g_tkT, 1u);
            t = __shfl_sync(0xffffffffu, t, 0);
            if (t >= NT_T) break;
            tensor_tile(t, lane, out);
        }
        for (;;) {
            int t;
            if (lane == 0) t = (int)atomicAdd(&g_tkD, 1u);
            t = __shfl_sync(0xffffffffu, t, 0);
            if (t >= NT_D) break;
            tensor_tile(NT_T + t, lane, out);
        }
    } else {
        uint4* As = s_a[wid - 4];
        for (;;) {
            int t;
            if (lane == 0) t = (int)atomicAdd(&g_tkD, 1u);
            t = __shfl_sync(0xffffffffu, t, 0);
            if (t >= NT_D) break;
            dp4a_tile(NT_T + t, lane, As, out);
        }
        for (;;) {
            int t;
            if (lane == 0) t = (int)atomicAdd(&g_tkT, 1u);
            t = __shfl_sync(0xffffffffu, t, 0);
            if (t >= NT_T) break;
            dp4a_tile(t, lane, As, out);
        }
    }
}

// ---------------- launcher ----------------
extern "C" void kernel_launch(void* const* d_in, const int* in_sizes, int n_in,
                              void* d_out, int out_size) {
    const float* inp    = (const float*)d_in[0];  // [16,128,32,32]
    const float* weight = (const float*)d_in[1];  // [256,128,3,3]
    float* out          = (float*)d_out;          // [16,256,32,32]

    const int nw = COUT * DTOT;
    const int n4 = 16 * 128 * (PADIMG / 4);

    k_minmax<<<256, 256>>>(weight, nw);
    k_quant<<<(nw + 255) / 256, 256>>>(weight);
    k_pad<<<(n4 + 255) / 256, 256>>>(inp);
    k_im2col<<<RCH * 64, 256>>>();
    k_onn_main<<<NCTA, 256>>>(out);
}